// round 13
// baseline (speedup 1.0000x reference)
#include <cuda_runtime.h>
#include <cuda_fp16.h>
#include <cstdint>
#include <math.h>

#define T_SEQ 4096
#define HIDDEN 2048
#define NHEADS 16
#define HEAD_DIM 128
#define SOFTCAP 50.0f
#define ATT_SCALE 0.0625f   // 256^-0.5

// ---------------- scratch (device globals; allocation-free) ----------------
__device__ __half g_xh[(size_t)T_SEQ * HIDDEN];      // X in fp16
__device__ __half g_ah[(size_t)T_SEQ * HIDDEN];      // attention out (fp16)
__device__ __half g_wth[4u * HIDDEN * HIDDEN];       // transposed weights (fp16)
__device__ __half g_qkvh[3u * T_SEQ * HIDDEN];       // q,k,v fp16 (roped in place)

// ======================= PTX helpers =======================================
__device__ __forceinline__ uint32_t smem_u32(const void* p) {
    uint32_t a;
    asm("{ .reg .u64 t; cvta.to.shared.u64 t, %1; cvt.u32.u64 %0, t; }"
        : "=r"(a) : "l"(p));
    return a;
}
__device__ __forceinline__ void cp_async16(uint32_t s, const void* g) {
    asm volatile("cp.async.cg.shared.global [%0], [%1], 16;" :: "r"(s), "l"(g));
}
#define CP_COMMIT() asm volatile("cp.async.commit_group;" ::: "memory")
#define CP_WAIT1()  asm volatile("cp.async.wait_group 1;" ::: "memory")
#define CP_WAIT0()  asm volatile("cp.async.wait_group 0;" ::: "memory")

__device__ __forceinline__ void ldmx4(uint32_t* r, uint32_t addr) {
    asm volatile("ldmatrix.sync.aligned.m8n8.x4.shared.b16 {%0,%1,%2,%3}, [%4];"
        : "=r"(r[0]), "=r"(r[1]), "=r"(r[2]), "=r"(r[3]) : "r"(addr));
}
__device__ __forceinline__ void ldmx4t(uint32_t* r, uint32_t addr) {
    asm volatile("ldmatrix.sync.aligned.m8n8.x4.trans.shared.b16 {%0,%1,%2,%3}, [%4];"
        : "=r"(r[0]), "=r"(r[1]), "=r"(r[2]), "=r"(r[3]) : "r"(addr));
}
__device__ __forceinline__ void mma_f16(float* d, const uint32_t* a,
                                        uint32_t b0, uint32_t b1) {
    asm volatile("mma.sync.aligned.m16n8k16.row.col.f32.f16.f16.f32 "
        "{%0,%1,%2,%3}, {%4,%5,%6,%7}, {%8,%9}, {%0,%1,%2,%3};"
        : "+f"(d[0]), "+f"(d[1]), "+f"(d[2]), "+f"(d[3])
        : "r"(a[0]), "r"(a[1]), "r"(a[2]), "r"(a[3]), "r"(b0), "r"(b1));
}
__device__ __forceinline__ uint32_t pack_h2(float lo, float hi) {
    __half2 v;
    v.x = __float2half(lo);
    v.y = __float2half(hi);
    return *(uint32_t*)&v;
}
__device__ __forceinline__ uint32_t swz(int row, int cb) {
    return (uint32_t)(row * 256 + (cb ^ ((row & 7) * 16)));
}

// ---------------- conversions ----------------------------------------------
__global__ __launch_bounds__(256) void cvt_half(const float* __restrict__ in,
                                                __half* __restrict__ oh) {
    int i = (blockIdx.x * 256 + threadIdx.x) * 4;
    float4 v = *(const float4*)&in[i];
    oh[i + 0] = __float2half(v.x);
    oh[i + 1] = __float2half(v.y);
    oh[i + 2] = __float2half(v.z);
    oh[i + 3] = __float2half(v.w);
}

// fused 4-way transpose 2048x2048 fp32 -> fp16 at [n][k]; z selects matrix
__global__ __launch_bounds__(256) void transpose_half4(
    const float* __restrict__ w0, const float* __restrict__ w1,
    const float* __restrict__ w2, const float* __restrict__ w3,
    __half* __restrict__ out)
{
    __shared__ float t[32][33];
    const float* in = (blockIdx.z == 0) ? w0 : (blockIdx.z == 1) ? w1
                    : (blockIdx.z == 2) ? w2 : w3;
    __half* o = out + (size_t)blockIdx.z * HIDDEN * HIDDEN;
    int x = blockIdx.x * 32 + threadIdx.x;
    int y = blockIdx.y * 32 + threadIdx.y;
#pragma unroll
    for (int j = 0; j < 4; j++)
        t[threadIdx.y + 8 * j][threadIdx.x] = in[(size_t)(y + 8 * j) * HIDDEN + x];
    __syncthreads();
    x = blockIdx.y * 32 + threadIdx.x;
    y = blockIdx.x * 32 + threadIdx.y;
#pragma unroll
    for (int j = 0; j < 4; j++)
        o[(size_t)(y + 8 * j) * HIDDEN + x] = __float2half(t[threadIdx.x][threadIdx.y + 8 * j]);
}

// ---------------- fp16 single-pass mma GEMM (2-stage, FROZEN @R11) ---------
// C[z] = A @ B[z]^T.  Output: fp16 (Ch0 != 0) or fp32 (C0).
// Tile 128x128, BK=32, 2-stage cp.async; 8 warps (2m x 4n), 2 CTAs/SM.
#define GS_AH 0
#define GS_BH 10240
#define GS_STAGE 20480
#define GS_TOTAL (2 * GS_STAGE)
#define G_KCHUNKS (HIDDEN / 32)

__global__ __launch_bounds__(256, 2) void gemm_mma(
    const __half* __restrict__ Ah,
    const __half* __restrict__ B0,
    float* __restrict__ C0, __half* __restrict__ Ch0,
    size_t bStrideZ, size_t cStrideZ)
{
    extern __shared__ char sm[];
    const uint32_t sb = smem_u32(sm);
    const int tid = threadIdx.x;
    const int lane = tid & 31;
    const int wid = tid >> 5;
    const int wm = wid & 1;
    const int wn = wid >> 1;
    const int bm = blockIdx.y * 128;
    const int bn = blockIdx.x * 128;
    const __half* B = B0 + (size_t)blockIdx.z * bStrideZ;

    float acc[4][4][4];
#pragma unroll
    for (int a = 0; a < 4; a++)
#pragma unroll
        for (int b = 0; b < 4; b++)
#pragma unroll
            for (int c = 0; c < 4; c++) acc[a][b][c] = 0.f;

    auto issue = [&](int chunk) {
        uint32_t st = sb + (chunk & 1) * GS_STAGE;
        int k0 = chunk * 32;
#pragma unroll
        for (int p = 0; p < 2; p++) {
            int idx = tid + p * 256;
            int row = idx >> 2, c = idx & 3;
            uint32_t soff = row * 80 + c * 16;
            size_t ga = (size_t)(bm + row) * HIDDEN + k0 + c * 8;
            size_t gb = (size_t)(bn + row) * HIDDEN + k0 + c * 8;
            cp_async16(st + GS_AH + soff, Ah + ga);
            cp_async16(st + GS_BH + soff, B + gb);
        }
    };

    const uint32_t aBase = (uint32_t)(wm * 64 + (lane & 15)) * 80 + (lane >> 4) * 16;
    const uint32_t bBase = (uint32_t)(wn * 32 + ((lane >> 4) & 1) * 8 + (lane & 7)) * 80
                         + ((lane >> 3) & 1) * 16;

    issue(0); CP_COMMIT();

    for (int i = 0; i < G_KCHUNKS; i++) {
        if (i + 1 < G_KCHUNKS) { issue(i + 1); CP_COMMIT(); CP_WAIT1(); }
        else CP_WAIT0();
        __syncthreads();
        uint32_t st = sb + (i & 1) * GS_STAGE;
#pragma unroll
        for (int kk = 0; kk < 2; kk++) {
            uint32_t aH[4][4], bH[2][4];
#pragma unroll
            for (int mt = 0; mt < 4; mt++)
                ldmx4(aH[mt], st + GS_AH + aBase + mt * 1280 + kk * 32);
#pragma unroll
            for (int np = 0; np < 2; np++)
                ldmx4(bH[np], st + GS_BH + bBase + np * 1280 + kk * 32);
#pragma unroll
            for (int mt = 0; mt < 4; mt++)
#pragma unroll
                for (int nt = 0; nt < 4; nt++)
                    mma_f16(acc[mt][nt], aH[mt],
                            bH[nt >> 1][(nt & 1) * 2],
                            bH[nt >> 1][(nt & 1) * 2 + 1]);
        }
        __syncthreads();
    }

    const int g = lane >> 2, t2 = (lane & 3) * 2;
    if (Ch0) {
        __half* C = Ch0 + (size_t)blockIdx.z * cStrideZ;
        uint32_t* Cp = (uint32_t*)C;
#pragma unroll
        for (int mt = 0; mt < 4; mt++) {
            int mrow = bm + wm * 64 + mt * 16 + g;
#pragma unroll
            for (int nt = 0; nt < 4; nt++) {
                int ncol = bn + wn * 32 + nt * 8 + t2;
                Cp[((size_t)mrow * HIDDEN + ncol) >> 1] =
                    pack_h2(acc[mt][nt][0], acc[mt][nt][1]);
                Cp[((size_t)(mrow + 8) * HIDDEN + ncol) >> 1] =
                    pack_h2(acc[mt][nt][2], acc[mt][nt][3]);
            }
        }
    } else {
        float* C = C0 + (size_t)blockIdx.z * cStrideZ;
#pragma unroll
        for (int mt = 0; mt < 4; mt++) {
            int mrow = bm + wm * 64 + mt * 16 + g;
#pragma unroll
            for (int nt = 0; nt < 4; nt++) {
                int ncol = bn + wn * 32 + nt * 8 + t2;
                *(float2*)&C[(size_t)mrow * HIDDEN + ncol] =
                    make_float2(acc[mt][nt][0], acc[mt][nt][1]);
                *(float2*)&C[(size_t)(mrow + 8) * HIDDEN + ncol] =
                    make_float2(acc[mt][nt][2], acc[mt][nt][3]);
            }
        }
    }
}

// --------- in-place fp16 RoPE on q,k (half2-vectorized, FROZEN) ------------
__global__ __launch_bounds__(256) void rope_qk() {
    int idx = blockIdx.x * blockDim.x + threadIdx.x;   // 2*4096*16*32
    int d2 = idx & 31;                                  // half2 pair: d = 2*d2, 2*d2+1
    int h  = (idx >> 5) & 15;
    int t  = (idx >> 9) & (T_SEQ - 1);
    int w  = idx >> 21;                                 // 0=q, 1=k
    __half* base = g_qkvh + (size_t)w * T_SEQ * HIDDEN
                 + (size_t)t * HIDDEN + h * HEAD_DIM;

    int d0 = 2 * d2;
    float f0 = powf(10000.0f, -(float)d0 * (1.0f / 64.0f));
    float f1 = f0 * 0.86596432f;                        // * 10000^(-1/64)
    float c0, s0, c1, s1;
    sincosf((float)t * f0, &s0, &c0);
    sincosf((float)t * f1, &s1, &c1);

    __half2 lo = *(__half2*)(base + d0);
    __half2 hi = *(__half2*)(base + d0 + 64);
    float x1a = __half2float(lo.x), x1b = __half2float(lo.y);
    float x2a = __half2float(hi.x), x2b = __half2float(hi.y);

    *(uint32_t*)(base + d0)      = pack_h2(x1a * c0 - x2a * s0, x1b * c1 - x2b * s1);
    *(uint32_t*)(base + d0 + 64) = pack_h2(x2a * c0 + x1a * s0, x2b * c1 + x1b * s1);
}

// ---------------- flash attention, fp16, 3-stage KV, ONE sync/tile ---------
// 256 threads (8 warps), BQ=128; 64-key tiles, 3-stage KV prefetch.
// smem: QH 0 (32KB); KV stage s at 32768 + s*32768: KH +0, VH +16384. 128KB.
#define AT_QH 0
#define AT_KV0 32768
#define AT_KVS 32768
#define AT_SMEM 131072

// softcap: tanh(u) ~ u*(1 - u^2/3) for |u| <~ 0.1 (u = s*SCALE/50):
// p = exp(50*tanh(u)) = 2^( u*(72.134752 - 24.044917*u^2) )
#define SC_K1 0.00125f         /* ATT_SCALE / 50 */
#define SC_A  72.134752f       /* 50 * log2(e) */
#define SC_B  24.044917f       /* 50 * log2(e) / 3 */

__global__ __launch_bounds__(256, 1) void flash_mma() {
    extern __shared__ char sm[];
    const uint32_t sb = smem_u32(sm);
    const int tid = threadIdx.x;
    const int lane = tid & 31;
    const int w = tid >> 5;
    const int h = blockIdx.y;
    const int qb = (gridDim.x - 1) - blockIdx.x;       // heavy blocks first

    const __half* Qg = g_qkvh;
    const __half* Kg = g_qkvh + (size_t)T_SEQ * HIDDEN;
    const __half* Vg = g_qkvh + 2u * T_SEQ * HIDDEN;

    const int g = lane >> 2, t4 = lane & 3;
    const int LAST = 2 * qb + 1;

    const int krow = tid >> 2, kcb = (tid & 3) * 4;

    auto issue_kv = [&](int kb) {
        uint32_t st = sb + AT_KV0 + (kb % 3) * AT_KVS;
        size_t gk = (size_t)(kb * 64 + krow) * HIDDEN + h * HEAD_DIM;
#pragma unroll
        for (int j = 0; j < 4; j++) {
            int c = kcb + j;
            uint32_t off = swz(krow, c * 16);
            cp_async16(st + 0     + off, Kg + gk + c * 8);
            cp_async16(st + 16384 + off, Vg + gk + c * 8);
        }
    };

    {
        int lrow = tid >> 1, cb2 = (tid & 1) * 8;
        size_t gq = (size_t)(qb * 128 + lrow) * HIDDEN + h * HEAD_DIM;
#pragma unroll
        for (int j = 0; j < 8; j++) {
            int c = cb2 + j;
            cp_async16(sb + AT_QH + swz(lrow, c * 16), Qg + gq + c * 8);
        }
        issue_kv(0);
        CP_COMMIT();
        issue_kv(1);          // LAST >= 1 always
        CP_COMMIT();
    }

    float O[16][4];
#pragma unroll
    for (int i = 0; i < 16; i++)
#pragma unroll
        for (int c = 0; c < 4; c++) O[i][c] = 0.f;
    float den0 = 0.f, den1 = 0.f;
    uint32_t qF[8][4];

    const int aRow = w * 16 + (lane & 15);
    const int aHalf = (lane >> 4) * 16;
    const int bRowBase = ((lane >> 4) & 1) * 8 + (lane & 7);
    const int bHalf = ((lane >> 3) & 1) * 16;
    const int vRowBase = ((lane >> 3) & 1) * 8 + (lane & 7);
    const int vHalf = ((lane >> 4) & 1) * 16;

    for (int kb = 0; kb <= LAST; kb++) {
        // wait for stage kb (leave at most 1 younger group in flight)
        if (kb + 1 <= LAST) CP_WAIT1(); else CP_WAIT0();
        __syncthreads();   // all warps done with stage (kb-1)%3 AND stage kb visible
        if (kb + 2 <= LAST) { issue_kv(kb + 2); CP_COMMIT(); }   // writes free buffer

        if (kb == 0) {
#pragma unroll
            for (int s = 0; s < 8; s++)
                ldmx4(qF[s], sb + AT_QH + swz(aRow, s * 32 + aHalf));
        }

        const uint32_t st = sb + AT_KV0 + (kb % 3) * AT_KVS;

        // ---- S = Q K^T ----
        float S[8][4];
#pragma unroll
        for (int i = 0; i < 8; i++)
#pragma unroll
            for (int c = 0; c < 4; c++) S[i][c] = 0.f;

#pragma unroll
        for (int s = 0; s < 8; s++) {
            uint32_t bh[4][4];
#pragma unroll
            for (int p = 0; p < 4; p++)
                ldmx4(bh[p], st + swz(bRowBase + p * 16, s * 32 + bHalf));
#pragma unroll
            for (int p = 0; p < 4; p++)
#pragma unroll
                for (int hf = 0; hf < 2; hf++)
                    mma_f16(S[p * 2 + hf], qF[s], bh[p][hf * 2], bh[p][hf * 2 + 1]);
        }

        // ---- softcap (tanh poly) + causal + exp2 ----
        const int rowg = qb * 128 + w * 16 + g;
        const bool diag = (kb >= 2 * qb);
#pragma unroll
        for (int nt = 0; nt < 8; nt++) {
#pragma unroll
            for (int c = 0; c < 4; c++) {
                float u = S[nt][c] * SC_K1;
                float arg = u * fmaf(u * u, -SC_B, SC_A);
                float p = exp2f(arg);
                if (diag) {
                    int col = kb * 64 + nt * 8 + 2 * t4 + (c & 1);
                    int row = rowg + (c >> 1) * 8;
                    if (col > row) p = 0.f;
                }
                S[nt][c] = p;
                if (c < 2) den0 += p; else den1 += p;
            }
        }

        uint32_t pH[4][4];
#pragma unroll
        for (int s2 = 0; s2 < 4; s2++) {
            pH[s2][0] = pack_h2(S[2*s2][0],   S[2*s2][1]);
            pH[s2][1] = pack_h2(S[2*s2][2],   S[2*s2][3]);
            pH[s2][2] = pack_h2(S[2*s2+1][0], S[2*s2+1][1]);
            pH[s2][3] = pack_h2(S[2*s2+1][2], S[2*s2+1][3]);
        }

        // ---- O += P V ----  (no trailing sync: 3rd stage removes the hazard)
#pragma unroll
        for (int s2 = 0; s2 < 4; s2++) {
            int vRow = s2 * 16 + vRowBase;
#pragma unroll
            for (int dp = 0; dp < 8; dp++) {
                uint32_t vh4[4];
                ldmx4t(vh4, st + 16384 + swz(vRow, dp * 32 + vHalf));
#pragma unroll
                for (int hf = 0; hf < 2; hf++)
                    mma_f16(O[dp * 2 + hf], pH[s2], vh4[hf * 2], vh4[hf * 2 + 1]);
            }
        }
    }

    den0 += __shfl_xor_sync(0xFFFFFFFF, den0, 1);
    den0 += __shfl_xor_sync(0xFFFFFFFF, den0, 2);
    den1 += __shfl_xor_sync(0xFFFFFFFF, den1, 1);
    den1 += __shfl_xor_sync(0xFFFFFFFF, den1, 2);
    float inv0 = 1.0f / den0, inv1 = 1.0f / den1;

    const int row0 = qb * 128 + w * 16 + g;
    uint32_t* ahp = (uint32_t*)g_ah;
#pragma unroll
    for (int dt = 0; dt < 16; dt++) {
        int col = h * HEAD_DIM + dt * 8 + 2 * t4;
        size_t o0 = ((size_t)row0 * HIDDEN + col) >> 1;
        size_t o1 = ((size_t)(row0 + 8) * HIDDEN + col) >> 1;
        ahp[o0] = pack_h2(O[dt][0] * inv0, O[dt][1] * inv0);
        ahp[o1] = pack_h2(O[dt][2] * inv1, O[dt][3] * inv1);
    }
}

// ---------------- launch ----------------------------------------------------
extern "C" void kernel_launch(void* const* d_in, const int* in_sizes, int n_in,
                              void* d_out, int out_size) {
    const float* X  = (const float*)d_in[0];
    const float* Wq = (const float*)d_in[1];
    const float* Wk = (const float*)d_in[2];
    const float* Wv = (const float*)d_in[3];
    const float* Wo = (const float*)d_in[4];
    float* out = (float*)d_out;

    __half *xh, *ah, *wth, *qkvh;
    cudaGetSymbolAddress((void**)&xh, g_xh);
    cudaGetSymbolAddress((void**)&ah, g_ah);
    cudaGetSymbolAddress((void**)&wth, g_wth);
    cudaGetSymbolAddress((void**)&qkvh, g_qkvh);

    cudaFuncSetAttribute(gemm_mma, cudaFuncAttributeMaxDynamicSharedMemorySize, GS_TOTAL);
    cudaFuncSetAttribute(flash_mma, cudaFuncAttributeMaxDynamicSharedMemorySize, AT_SMEM);

    const size_t WSTRIDE = (size_t)HIDDEN * HIDDEN;

    transpose_half4<<<dim3(HIDDEN / 32, HIDDEN / 32, 4), dim3(32, 8)>>>(Wq, Wk, Wv, Wo, wth);
    cvt_half<<<(T_SEQ * HIDDEN) / 1024, 256>>>(X, xh);

    // fused QKV, fp16 output directly into g_qkvh
    gemm_mma<<<dim3(HIDDEN / 128, T_SEQ / 128, 3), 256, GS_TOTAL>>>(
        xh, wth, nullptr, qkvh, WSTRIDE, (size_t)T_SEQ * HIDDEN);

    rope_qk<<<(2u * T_SEQ * NHEADS * 32) / 256, 256>>>();

    flash_mma<<<dim3(T_SEQ / 128, NHEADS), 256, AT_SMEM>>>();

    // Wo GEMM, fp32 output to harness buffer
    gemm_mma<<<dim3(HIDDEN / 128, T_SEQ / 128, 1), 256, GS_TOTAL>>>(
        ah, wth + 3 * WSTRIDE, out, nullptr, 0, 0);
}

// round 14
// speedup vs baseline: 1.0055x; 1.0055x over previous
#include <cuda_runtime.h>
#include <cuda_fp16.h>
#include <cstdint>
#include <math.h>

#define T_SEQ 4096
#define HIDDEN 2048
#define NHEADS 16
#define HEAD_DIM 128
#define SOFTCAP 50.0f
#define ATT_SCALE 0.0625f   // 256^-0.5

// ---------------- scratch (device globals; allocation-free) ----------------
__device__ __half g_xh[(size_t)T_SEQ * HIDDEN];      // X in fp16
__device__ __half g_ah[(size_t)T_SEQ * HIDDEN];      // attention out (fp16)
__device__ __half g_wth[4u * HIDDEN * HIDDEN];       // transposed weights (fp16)
__device__ __half g_qkvh[3u * T_SEQ * HIDDEN];       // q,k,v fp16 (roped in place)

// ======================= PTX helpers =======================================
__device__ __forceinline__ uint32_t smem_u32(const void* p) {
    uint32_t a;
    asm("{ .reg .u64 t; cvta.to.shared.u64 t, %1; cvt.u32.u64 %0, t; }"
        : "=r"(a) : "l"(p));
    return a;
}
__device__ __forceinline__ void cp_async16(uint32_t s, const void* g) {
    asm volatile("cp.async.cg.shared.global [%0], [%1], 16;" :: "r"(s), "l"(g));
}
#define CP_COMMIT() asm volatile("cp.async.commit_group;" ::: "memory")
#define CP_WAIT1()  asm volatile("cp.async.wait_group 1;" ::: "memory")
#define CP_WAIT0()  asm volatile("cp.async.wait_group 0;" ::: "memory")

__device__ __forceinline__ void ldmx4(uint32_t* r, uint32_t addr) {
    asm volatile("ldmatrix.sync.aligned.m8n8.x4.shared.b16 {%0,%1,%2,%3}, [%4];"
        : "=r"(r[0]), "=r"(r[1]), "=r"(r[2]), "=r"(r[3]) : "r"(addr));
}
__device__ __forceinline__ void ldmx4t(uint32_t* r, uint32_t addr) {
    asm volatile("ldmatrix.sync.aligned.m8n8.x4.trans.shared.b16 {%0,%1,%2,%3}, [%4];"
        : "=r"(r[0]), "=r"(r[1]), "=r"(r[2]), "=r"(r[3]) : "r"(addr));
}
__device__ __forceinline__ void mma_f16(float* d, const uint32_t* a,
                                        uint32_t b0, uint32_t b1) {
    asm volatile("mma.sync.aligned.m16n8k16.row.col.f32.f16.f16.f32 "
        "{%0,%1,%2,%3}, {%4,%5,%6,%7}, {%8,%9}, {%0,%1,%2,%3};"
        : "+f"(d[0]), "+f"(d[1]), "+f"(d[2]), "+f"(d[3])
        : "r"(a[0]), "r"(a[1]), "r"(a[2]), "r"(a[3]), "r"(b0), "r"(b1));
}
__device__ __forceinline__ uint32_t pack_h2(float lo, float hi) {
    __half2 v;
    v.x = __float2half(lo);
    v.y = __float2half(hi);
    return *(uint32_t*)&v;
}
__device__ __forceinline__ uint32_t swz(int row, int cb) {
    return (uint32_t)(row * 256 + (cb ^ ((row & 7) * 16)));
}

// ------- fused prep: 4-way weight transpose (fp32->fp16 [n][k]) + X cvt ----
// flat grid: blocks [0,16384) transpose (idx -> bx, by, z); [16384, 24576) cvt.
#define PREP_TBLOCKS 16384
#define PREP_BLOCKS  24576

__global__ __launch_bounds__(256) void prep_kernel(
    const float* __restrict__ w0, const float* __restrict__ w1,
    const float* __restrict__ w2, const float* __restrict__ w3,
    __half* __restrict__ wt,
    const float* __restrict__ X, __half* __restrict__ xh)
{
    __shared__ float t[32][33];
    const int bidx = blockIdx.x;
    const int tx = threadIdx.x, ty = threadIdx.y;

    if (bidx < PREP_TBLOCKS) {
        int bx = bidx & 63;
        int by = (bidx >> 6) & 63;
        int z  = bidx >> 12;
        const float* in = (z == 0) ? w0 : (z == 1) ? w1 : (z == 2) ? w2 : w3;
        __half* o = wt + (size_t)z * HIDDEN * HIDDEN;
        int x = bx * 32 + tx;
        int y = by * 32 + ty;
#pragma unroll
        for (int j = 0; j < 4; j++)
            t[ty + 8 * j][tx] = in[(size_t)(y + 8 * j) * HIDDEN + x];
        __syncthreads();
        x = by * 32 + tx;
        y = bx * 32 + ty;
#pragma unroll
        for (int j = 0; j < 4; j++)
            o[(size_t)(y + 8 * j) * HIDDEN + x] = __float2half(t[tx][ty + 8 * j]);
    } else {
        int tid = ty * 32 + tx;
        int i = ((bidx - PREP_TBLOCKS) * 256 + tid) * 4;
        float4 v = *(const float4*)&X[i];
        xh[i + 0] = __float2half(v.x);
        xh[i + 1] = __float2half(v.y);
        xh[i + 2] = __float2half(v.z);
        xh[i + 3] = __float2half(v.w);
    }
}

// ---------------- fp16 single-pass mma GEMM (2-stage, FROZEN @R11) ---------
// C[z] = A @ B[z]^T.  Output: fp16 (Ch0 != 0) or fp32 (C0).
// Tile 128x128, BK=32, 2-stage cp.async; 8 warps (2m x 4n), 2 CTAs/SM.
#define GS_AH 0
#define GS_BH 10240
#define GS_STAGE 20480
#define GS_TOTAL (2 * GS_STAGE)
#define G_KCHUNKS (HIDDEN / 32)

__global__ __launch_bounds__(256, 2) void gemm_mma(
    const __half* __restrict__ Ah,
    const __half* __restrict__ B0,
    float* __restrict__ C0, __half* __restrict__ Ch0,
    size_t bStrideZ, size_t cStrideZ)
{
    extern __shared__ char sm[];
    const uint32_t sb = smem_u32(sm);
    const int tid = threadIdx.x;
    const int lane = tid & 31;
    const int wid = tid >> 5;
    const int wm = wid & 1;
    const int wn = wid >> 1;
    const int bm = blockIdx.y * 128;
    const int bn = blockIdx.x * 128;
    const __half* B = B0 + (size_t)blockIdx.z * bStrideZ;

    float acc[4][4][4];
#pragma unroll
    for (int a = 0; a < 4; a++)
#pragma unroll
        for (int b = 0; b < 4; b++)
#pragma unroll
            for (int c = 0; c < 4; c++) acc[a][b][c] = 0.f;

    auto issue = [&](int chunk) {
        uint32_t st = sb + (chunk & 1) * GS_STAGE;
        int k0 = chunk * 32;
#pragma unroll
        for (int p = 0; p < 2; p++) {
            int idx = tid + p * 256;
            int row = idx >> 2, c = idx & 3;
            uint32_t soff = row * 80 + c * 16;
            size_t ga = (size_t)(bm + row) * HIDDEN + k0 + c * 8;
            size_t gb = (size_t)(bn + row) * HIDDEN + k0 + c * 8;
            cp_async16(st + GS_AH + soff, Ah + ga);
            cp_async16(st + GS_BH + soff, B + gb);
        }
    };

    const uint32_t aBase = (uint32_t)(wm * 64 + (lane & 15)) * 80 + (lane >> 4) * 16;
    const uint32_t bBase = (uint32_t)(wn * 32 + ((lane >> 4) & 1) * 8 + (lane & 7)) * 80
                         + ((lane >> 3) & 1) * 16;

    issue(0); CP_COMMIT();

    for (int i = 0; i < G_KCHUNKS; i++) {
        if (i + 1 < G_KCHUNKS) { issue(i + 1); CP_COMMIT(); CP_WAIT1(); }
        else CP_WAIT0();
        __syncthreads();
        uint32_t st = sb + (i & 1) * GS_STAGE;
#pragma unroll
        for (int kk = 0; kk < 2; kk++) {
            uint32_t aH[4][4], bH[2][4];
#pragma unroll
            for (int mt = 0; mt < 4; mt++)
                ldmx4(aH[mt], st + GS_AH + aBase + mt * 1280 + kk * 32);
#pragma unroll
            for (int np = 0; np < 2; np++)
                ldmx4(bH[np], st + GS_BH + bBase + np * 1280 + kk * 32);
#pragma unroll
            for (int mt = 0; mt < 4; mt++)
#pragma unroll
                for (int nt = 0; nt < 4; nt++)
                    mma_f16(acc[mt][nt], aH[mt],
                            bH[nt >> 1][(nt & 1) * 2],
                            bH[nt >> 1][(nt & 1) * 2 + 1]);
        }
        __syncthreads();
    }

    const int g = lane >> 2, t2 = (lane & 3) * 2;
    if (Ch0) {
        __half* C = Ch0 + (size_t)blockIdx.z * cStrideZ;
        uint32_t* Cp = (uint32_t*)C;
#pragma unroll
        for (int mt = 0; mt < 4; mt++) {
            int mrow = bm + wm * 64 + mt * 16 + g;
#pragma unroll
            for (int nt = 0; nt < 4; nt++) {
                int ncol = bn + wn * 32 + nt * 8 + t2;
                Cp[((size_t)mrow * HIDDEN + ncol) >> 1] =
                    pack_h2(acc[mt][nt][0], acc[mt][nt][1]);
                Cp[((size_t)(mrow + 8) * HIDDEN + ncol) >> 1] =
                    pack_h2(acc[mt][nt][2], acc[mt][nt][3]);
            }
        }
    } else {
        float* C = C0 + (size_t)blockIdx.z * cStrideZ;
#pragma unroll
        for (int mt = 0; mt < 4; mt++) {
            int mrow = bm + wm * 64 + mt * 16 + g;
#pragma unroll
            for (int nt = 0; nt < 4; nt++) {
                int ncol = bn + wn * 32 + nt * 8 + t2;
                *(float2*)&C[(size_t)mrow * HIDDEN + ncol] =
                    make_float2(acc[mt][nt][0], acc[mt][nt][1]);
                *(float2*)&C[(size_t)(mrow + 8) * HIDDEN + ncol] =
                    make_float2(acc[mt][nt][2], acc[mt][nt][3]);
            }
        }
    }
}

// --------- in-place fp16 RoPE on q,k (half2-vectorized, FROZEN) ------------
__global__ __launch_bounds__(256) void rope_qk() {
    int idx = blockIdx.x * blockDim.x + threadIdx.x;   // 2*4096*16*32
    int d2 = idx & 31;                                  // half2 pair: d = 2*d2, 2*d2+1
    int h  = (idx >> 5) & 15;
    int t  = (idx >> 9) & (T_SEQ - 1);
    int w  = idx >> 21;                                 // 0=q, 1=k
    __half* base = g_qkvh + (size_t)w * T_SEQ * HIDDEN
                 + (size_t)t * HIDDEN + h * HEAD_DIM;

    int d0 = 2 * d2;
    float f0 = powf(10000.0f, -(float)d0 * (1.0f / 64.0f));
    float f1 = f0 * 0.86596432f;                        // * 10000^(-1/64)
    float c0, s0, c1, s1;
    sincosf((float)t * f0, &s0, &c0);
    sincosf((float)t * f1, &s1, &c1);

    __half2 lo = *(__half2*)(base + d0);
    __half2 hi = *(__half2*)(base + d0 + 64);
    float x1a = __half2float(lo.x), x1b = __half2float(lo.y);
    float x2a = __half2float(hi.x), x2b = __half2float(hi.y);

    *(uint32_t*)(base + d0)      = pack_h2(x1a * c0 - x2a * s0, x1b * c1 - x2b * s1);
    *(uint32_t*)(base + d0 + 64) = pack_h2(x2a * c0 + x1a * s0, x2b * c1 + x1b * s1);
}

// ---------------- flash attention, single-pass fp16 (2-stage, R11 best) ----
// 256 threads (8 warps), BQ=128; 64-key tiles, 2-stage KV prefetch.
// smem: QH 0 (32KB); KV stage s at 32768 + s*32768: KH +0, VH +16384. 96KB.
#define AT_QH 0
#define AT_KV0 32768
#define AT_KVS 32768
#define AT_SMEM 98304

// softcap: tanh(u) ~ u*(1 - u^2/3) for |u| <~ 0.1 (u = s*SCALE/50):
// p = exp(50*tanh(u)) = 2^( u*(72.134752 - 24.044917*u^2) )
#define SC_K1 0.00125f         /* ATT_SCALE / 50 */
#define SC_A  72.134752f       /* 50 * log2(e) */
#define SC_B  24.044917f       /* 50 * log2(e) / 3 */

__global__ __launch_bounds__(256, 1) void flash_mma() {
    extern __shared__ char sm[];
    const uint32_t sb = smem_u32(sm);
    const int tid = threadIdx.x;
    const int lane = tid & 31;
    const int w = tid >> 5;
    const int h = blockIdx.y;
    const int qb = (gridDim.x - 1) - blockIdx.x;       // heavy blocks first

    const __half* Qg = g_qkvh;
    const __half* Kg = g_qkvh + (size_t)T_SEQ * HIDDEN;
    const __half* Vg = g_qkvh + 2u * T_SEQ * HIDDEN;

    const int g = lane >> 2, t4 = lane & 3;
    const int LAST = 2 * qb + 1;

    const int krow = tid >> 2, kcb = (tid & 3) * 4;

    auto issue_kv = [&](int kb) {
        uint32_t st = sb + AT_KV0 + (kb & 1) * AT_KVS;
        size_t gk = (size_t)(kb * 64 + krow) * HIDDEN + h * HEAD_DIM;
#pragma unroll
        for (int j = 0; j < 4; j++) {
            int c = kcb + j;
            uint32_t off = swz(krow, c * 16);
            cp_async16(st + 0     + off, Kg + gk + c * 8);
            cp_async16(st + 16384 + off, Vg + gk + c * 8);
        }
    };

    {
        int lrow = tid >> 1, cb2 = (tid & 1) * 8;
        size_t gq = (size_t)(qb * 128 + lrow) * HIDDEN + h * HEAD_DIM;
#pragma unroll
        for (int j = 0; j < 8; j++) {
            int c = cb2 + j;
            cp_async16(sb + AT_QH + swz(lrow, c * 16), Qg + gq + c * 8);
        }
        issue_kv(0);
        CP_COMMIT();
    }

    float O[16][4];
#pragma unroll
    for (int i = 0; i < 16; i++)
#pragma unroll
        for (int c = 0; c < 4; c++) O[i][c] = 0.f;
    float den0 = 0.f, den1 = 0.f;
    uint32_t qF[8][4];

    const int aRow = w * 16 + (lane & 15);
    const int aHalf = (lane >> 4) * 16;
    const int bRowBase = ((lane >> 4) & 1) * 8 + (lane & 7);
    const int bHalf = ((lane >> 3) & 1) * 16;
    const int vRowBase = ((lane >> 3) & 1) * 8 + (lane & 7);
    const int vHalf = ((lane >> 4) & 1) * 16;

    for (int kb = 0; kb <= LAST; kb++) {
        if (kb + 1 <= LAST) { issue_kv(kb + 1); CP_COMMIT(); CP_WAIT1(); }
        else CP_WAIT0();
        __syncthreads();

        if (kb == 0) {
#pragma unroll
            for (int s = 0; s < 8; s++)
                ldmx4(qF[s], sb + AT_QH + swz(aRow, s * 32 + aHalf));
        }

        const uint32_t st = sb + AT_KV0 + (kb & 1) * AT_KVS;

        // ---- S = Q K^T ----
        float S[8][4];
#pragma unroll
        for (int i = 0; i < 8; i++)
#pragma unroll
            for (int c = 0; c < 4; c++) S[i][c] = 0.f;

#pragma unroll
        for (int s = 0; s < 8; s++) {
            uint32_t bh[4][4];
#pragma unroll
            for (int p = 0; p < 4; p++)
                ldmx4(bh[p], st + swz(bRowBase + p * 16, s * 32 + bHalf));
#pragma unroll
            for (int p = 0; p < 4; p++)
#pragma unroll
                for (int hf = 0; hf < 2; hf++)
                    mma_f16(S[p * 2 + hf], qF[s], bh[p][hf * 2], bh[p][hf * 2 + 1]);
        }

        // ---- softcap (tanh poly) + causal + exp2 ----
        const int rowg = qb * 128 + w * 16 + g;
        const bool diag = (kb >= 2 * qb);
#pragma unroll
        for (int nt = 0; nt < 8; nt++) {
#pragma unroll
            for (int c = 0; c < 4; c++) {
                float u = S[nt][c] * SC_K1;
                float arg = u * fmaf(u * u, -SC_B, SC_A);
                float p = exp2f(arg);
                if (diag) {
                    int col = kb * 64 + nt * 8 + 2 * t4 + (c & 1);
                    int row = rowg + (c >> 1) * 8;
                    if (col > row) p = 0.f;
                }
                S[nt][c] = p;
                if (c < 2) den0 += p; else den1 += p;
            }
        }

        uint32_t pH[4][4];
#pragma unroll
        for (int s2 = 0; s2 < 4; s2++) {
            pH[s2][0] = pack_h2(S[2*s2][0],   S[2*s2][1]);
            pH[s2][1] = pack_h2(S[2*s2][2],   S[2*s2][3]);
            pH[s2][2] = pack_h2(S[2*s2+1][0], S[2*s2+1][1]);
            pH[s2][3] = pack_h2(S[2*s2+1][2], S[2*s2+1][3]);
        }

        // ---- O += P V ----
#pragma unroll
        for (int s2 = 0; s2 < 4; s2++) {
            int vRow = s2 * 16 + vRowBase;
#pragma unroll
            for (int dp = 0; dp < 8; dp++) {
                uint32_t vh4[4];
                ldmx4t(vh4, st + 16384 + swz(vRow, dp * 32 + vHalf));
#pragma unroll
                for (int hf = 0; hf < 2; hf++)
                    mma_f16(O[dp * 2 + hf], pH[s2], vh4[hf * 2], vh4[hf * 2 + 1]);
            }
        }
        __syncthreads();
    }

    den0 += __shfl_xor_sync(0xFFFFFFFF, den0, 1);
    den0 += __shfl_xor_sync(0xFFFFFFFF, den0, 2);
    den1 += __shfl_xor_sync(0xFFFFFFFF, den1, 1);
    den1 += __shfl_xor_sync(0xFFFFFFFF, den1, 2);
    float inv0 = 1.0f / den0, inv1 = 1.0f / den1;

    const int row0 = qb * 128 + w * 16 + g;
    uint32_t* ahp = (uint32_t*)g_ah;
#pragma unroll
    for (int dt = 0; dt < 16; dt++) {
        int col = h * HEAD_DIM + dt * 8 + 2 * t4;
        size_t o0 = ((size_t)row0 * HIDDEN + col) >> 1;
        size_t o1 = ((size_t)(row0 + 8) * HIDDEN + col) >> 1;
        ahp[o0] = pack_h2(O[dt][0] * inv0, O[dt][1] * inv0);
        ahp[o1] = pack_h2(O[dt][2] * inv1, O[dt][3] * inv1);
    }
}

// ---------------- launch ----------------------------------------------------
extern "C" void kernel_launch(void* const* d_in, const int* in_sizes, int n_in,
                              void* d_out, int out_size) {
    const float* X  = (const float*)d_in[0];
    const float* Wq = (const float*)d_in[1];
    const float* Wk = (const float*)d_in[2];
    const float* Wv = (const float*)d_in[3];
    const float* Wo = (const float*)d_in[4];
    float* out = (float*)d_out;

    __half *xh, *ah, *wth, *qkvh;
    cudaGetSymbolAddress((void**)&xh, g_xh);
    cudaGetSymbolAddress((void**)&ah, g_ah);
    cudaGetSymbolAddress((void**)&wth, g_wth);
    cudaGetSymbolAddress((void**)&qkvh, g_qkvh);

    cudaFuncSetAttribute(gemm_mma, cudaFuncAttributeMaxDynamicSharedMemorySize, GS_TOTAL);
    cudaFuncSetAttribute(flash_mma, cudaFuncAttributeMaxDynamicSharedMemorySize, AT_SMEM);

    const size_t WSTRIDE = (size_t)HIDDEN * HIDDEN;

    // fused weight transpose + X fp16 convert
    prep_kernel<<<PREP_BLOCKS, dim3(32, 8)>>>(Wq, Wk, Wv, Wo, wth, X, xh);

    // fused QKV, fp16 output directly into g_qkvh
    gemm_mma<<<dim3(HIDDEN / 128, T_SEQ / 128, 3), 256, GS_TOTAL>>>(
        xh, wth, nullptr, qkvh, WSTRIDE, (size_t)T_SEQ * HIDDEN);

    rope_qk<<<(2u * T_SEQ * NHEADS * 32) / 256, 256>>>();

    flash_mma<<<dim3(T_SEQ / 128, NHEADS), 256, AT_SMEM>>>();

    // Wo GEMM, fp32 output to harness buffer
    gemm_mma<<<dim3(HIDDEN / 128, T_SEQ / 128, 1), 256, GS_TOTAL>>>(
        ah, wth + 3 * WSTRIDE, out, nullptr, 0, 0);
}